// round 6
// baseline (speedup 1.0000x reference)
#include <cuda_runtime.h>
#include <cuda_bf16.h>

#define N_NODES 100000
#define N_EDGES 3200000
#define IN_CH   256

// Scratch (device globals: allocation APIs are forbidden)
__device__ float g_xm[N_NODES];    // x @ W_mlp
__device__ float g_xl[N_NODES];    // x @ W_lin
__device__ float g_xw[N_NODES];    // x @ W_gcn
__device__ float g_degf[N_NODES];  // in-degree (float, exact: deg << 2^24)
__device__ float g_h[N_NODES];     // rsqrt(deg+1) * xw
__device__ float g_gcn[N_NODES];   // accumulates sum_s h[s]
__device__ int   g_barcnt;         // software grid barrier (memset 0 per launch)

#define A_BLOCKS 592               // kernel A: 4 blocks/SM * 148 (62 regs ok)
#define A_WARPS  (A_BLOCKS * 8)
#define B_BLOCKS 1184              // kernel B: 8 blocks/SM * 148, <=32 regs
#define B_THREADS (B_BLOCKS * 256)
#define EQUADS   (N_EDGES / 4)     // 800000 int4 groups

// ---------------------------------------------------------------------------
__device__ __forceinline__ void dot3(const float4 a0, const float4 a1,
                                     const float4 m0, const float4 m1,
                                     const float4 l0, const float4 l1,
                                     const float4 g0, const float4 g1,
                                     float& sm, float& sl, float& sg) {
    sm = a0.x*m0.x + a0.y*m0.y + a0.z*m0.z + a0.w*m0.w
       + a1.x*m1.x + a1.y*m1.y + a1.z*m1.z + a1.w*m1.w;
    sl = a0.x*l0.x + a0.y*l0.y + a0.z*l0.z + a0.w*l0.w
       + a1.x*l1.x + a1.y*l1.y + a1.z*l1.z + a1.w*l1.w;
    sg = a0.x*g0.x + a0.y*g0.y + a0.z*g0.z + a0.w*g0.w
       + a1.x*g1.x + a1.y*g1.y + a1.z*g1.z + a1.w*g1.w;
}

// ---------------------------------------------------------------------------
// Kernel A: every block first strides the edge list (degree count), then
// strides the node list (3 fused dot products, warp per node, 4-node ILP).
__global__ void __launch_bounds__(256) kernelA(
        const float* __restrict__ x,
        const float* __restrict__ Wm,
        const float* __restrict__ Wl,
        const float* __restrict__ Wg,
        const int*   __restrict__ dst) {
    // ---- degree count: 4 edges per thread-iteration, grid-stride ----
    {
        int t = blockIdx.x * 256 + threadIdx.x;
        const int stride = A_BLOCKS * 256;
        const int4* d4p = (const int4*)dst;
        for (; t < EQUADS; t += stride) {
            int4 a = d4p[t];
            atomicAdd(&g_degf[a.x], 1.0f);
            atomicAdd(&g_degf[a.y], 1.0f);
            atomicAdd(&g_degf[a.z], 1.0f);
            atomicAdd(&g_degf[a.w], 1.0f);
        }
    }

    // ---- fused dots: warp per node, 4 nodes per iteration ----
    int wid  = (blockIdx.x * 256 + threadIdx.x) >> 5;
    int lane = threadIdx.x & 31;
    int i0 = lane, i1 = lane + 32;

    const float4* wm4 = (const float4*)Wm;
    const float4* wl4 = (const float4*)Wl;
    const float4* wg4 = (const float4*)Wg;
    float4 m0 = __ldg(&wm4[i0]), m1 = __ldg(&wm4[i1]);
    float4 l0 = __ldg(&wl4[i0]), l1 = __ldg(&wl4[i1]);
    float4 g0 = __ldg(&wg4[i0]), g1 = __ldg(&wg4[i1]);

    const int stride = A_WARPS;
    for (int n0 = wid; n0 < N_NODES; n0 += 4 * stride) {
        int n1 = n0 + stride;
        int n2 = n0 + 2 * stride;
        int n3 = n0 + 3 * stride;
        bool h1 = n1 < N_NODES, h2 = n2 < N_NODES, h3 = n3 < N_NODES;

        const float4* x0 = (const float4*)(x + (size_t)n0 * IN_CH);
        const float4* x1 = (const float4*)(x + (size_t)(h1 ? n1 : n0) * IN_CH);
        const float4* x2 = (const float4*)(x + (size_t)(h2 ? n2 : n0) * IN_CH);
        const float4* x3 = (const float4*)(x + (size_t)(h3 ? n3 : n0) * IN_CH);

        float4 a0 = x0[i0], a1 = x0[i1];
        float4 b0 = x1[i0], b1 = x1[i1];
        float4 c0 = x2[i0], c1 = x2[i1];
        float4 d0 = x3[i0], d1 = x3[i1];

        float smA, slA, sgA, smB, slB, sgB, smC, slC, sgC, smD, slD, sgD;
        dot3(a0, a1, m0, m1, l0, l1, g0, g1, smA, slA, sgA);
        dot3(b0, b1, m0, m1, l0, l1, g0, g1, smB, slB, sgB);
        dot3(c0, c1, m0, m1, l0, l1, g0, g1, smC, slC, sgC);
        dot3(d0, d1, m0, m1, l0, l1, g0, g1, smD, slD, sgD);

#pragma unroll
        for (int o = 16; o > 0; o >>= 1) {
            smA += __shfl_xor_sync(0xffffffffu, smA, o);
            slA += __shfl_xor_sync(0xffffffffu, slA, o);
            sgA += __shfl_xor_sync(0xffffffffu, sgA, o);
            smB += __shfl_xor_sync(0xffffffffu, smB, o);
            slB += __shfl_xor_sync(0xffffffffu, slB, o);
            sgB += __shfl_xor_sync(0xffffffffu, sgB, o);
            smC += __shfl_xor_sync(0xffffffffu, smC, o);
            slC += __shfl_xor_sync(0xffffffffu, slC, o);
            sgC += __shfl_xor_sync(0xffffffffu, sgC, o);
            smD += __shfl_xor_sync(0xffffffffu, smD, o);
            slD += __shfl_xor_sync(0xffffffffu, slD, o);
            sgD += __shfl_xor_sync(0xffffffffu, sgD, o);
        }
        if (lane == 0) {
            g_xm[n0] = smA; g_xl[n0] = slA; g_xw[n0] = sgA;
            if (h1) { g_xm[n1] = smB; g_xl[n1] = slB; g_xw[n1] = sgB; }
            if (h2) { g_xm[n2] = smC; g_xl[n2] = slC; g_xw[n2] = sgC; }
            if (h3) { g_xm[n3] = smD; g_xl[n3] = slD; g_xw[n3] = sgD; }
        }
    }
}

// ---------------------------------------------------------------------------
// Software grid barrier: monotonic arrival counter (zeroed per launch by a
// memset node). All B_BLOCKS are guaranteed co-resident (launch_bounds 8/SM),
// so spinning is deadlock-free.
__device__ __forceinline__ void grid_bar(int target) {
    __syncthreads();
    if (threadIdx.x == 0) {
        __threadfence();                      // publish this block's writes
        atomicAdd(&g_barcnt, 1);
        while (*(volatile int*)&g_barcnt < target) {
            __nanosleep(64);
        }
        __threadfence();                      // order subsequent reads
    }
    __syncthreads();
}

__device__ __forceinline__ float sigmoidf_(float v) {
    return 1.0f / (1.0f + expf(-v));
}

// ---------------------------------------------------------------------------
// Kernel B (persistent): h -> barrier -> msg -> barrier -> final.
__global__ void __launch_bounds__(256, 8) kernelB(
        const int*   __restrict__ src,
        const int*   __restrict__ dst,
        const float* __restrict__ alpha_p,
        const float* __restrict__ beta_p,
        const float* __restrict__ W_att,
        const float* __restrict__ b_att,
        float* __restrict__ out) {
    int tid = blockIdx.x * 256 + threadIdx.x;

    // ---- phase 1: h[n] = rsqrt(deg+1) * xw[n] ----
    for (int n = tid; n < N_NODES; n += B_THREADS) {
        g_h[n] = rsqrtf(g_degf[n] + 1.0f) * g_xw[n];
    }

    grid_bar(B_BLOCKS);

    // ---- phase 2: gcn[d] += h[s], 4 edges per iteration ----
    {
        const int4* s4p = (const int4*)src;
        const int4* d4p = (const int4*)dst;
        for (int t = tid; t < EQUADS; t += B_THREADS) {
            int4 s = s4p[t];
            int4 d = d4p[t];
            float h0 = __ldg(&g_h[s.x]);
            float h1 = __ldg(&g_h[s.y]);
            float h2 = __ldg(&g_h[s.z]);
            float h3 = __ldg(&g_h[s.w]);
            atomicAdd(&g_gcn[d.x], h0);
            atomicAdd(&g_gcn[d.y], h1);
            atomicAdd(&g_gcn[d.z], h2);
            atomicAdd(&g_gcn[d.w], h3);
        }
    }

    grid_bar(2 * B_BLOCKS);

    // ---- phase 3: final fusion ----
    float alpha = __ldg(alpha_p);
    float beta  = __ldg(beta_p);
    for (int n = tid; n < N_NODES; n += B_THREADS) {
        float degf = g_degf[n];
        float dinv = rsqrtf(degf + 1.0f);
        float gcn  = dinv * (g_gcn[n] + g_h[n]);   // h[n] = dinv*xw[n]

        float s1 = sigmoidf_(alpha * sqrtf(degf) + beta);
        float s2 = sigmoidf_(g_xm[n]);
        float s3 = sigmoidf_(gcn + g_xl[n]);

        float l0 = s1 * __ldg(&W_att[0]) + s2 * __ldg(&W_att[1]) + s3 * __ldg(&W_att[2]) + __ldg(&b_att[0]);
        float l1 = s1 * __ldg(&W_att[3]) + s2 * __ldg(&W_att[4]) + s3 * __ldg(&W_att[5]) + __ldg(&b_att[1]);
        float l2 = s1 * __ldg(&W_att[6]) + s2 * __ldg(&W_att[7]) + s3 * __ldg(&W_att[8]) + __ldg(&b_att[2]);

        float m  = fmaxf(l0, fmaxf(l1, l2));
        float e0 = expf(l0 - m), e1 = expf(l1 - m), e2 = expf(l2 - m);
        float inv = 1.0f / (e0 + e1 + e2);
        out[n] = (e0 * s1 + e1 * s2 + e2 * s3) * inv;
    }
}

// ---------------------------------------------------------------------------
extern "C" void kernel_launch(void* const* d_in, const int* in_sizes, int n_in,
                              void* d_out, int out_size) {
    const float* x     = (const float*)d_in[0];
    const int*   eidx  = (const int*)d_in[1];   // [2, N_EDGES] int32
    const float* alpha = (const float*)d_in[2];
    const float* beta  = (const float*)d_in[3];
    const float* Wm    = (const float*)d_in[4];
    const float* Wl    = (const float*)d_in[5];
    const float* Wg    = (const float*)d_in[6];
    const float* Watt  = (const float*)d_in[7];
    const float* batt  = (const float*)d_in[8];
    float* out = (float*)d_out;

    const int* src = eidx;            // edge_index[0]
    const int* dst = eidx + N_EDGES;  // edge_index[1]

    void *degf_ptr = nullptr, *gcn_ptr = nullptr, *bar_ptr = nullptr;
    cudaGetSymbolAddress(&degf_ptr, g_degf);
    cudaGetSymbolAddress(&gcn_ptr,  g_gcn);
    cudaGetSymbolAddress(&bar_ptr,  g_barcnt);
    cudaMemsetAsync(degf_ptr, 0, N_NODES * sizeof(float));
    cudaMemsetAsync(gcn_ptr,  0, N_NODES * sizeof(float));
    cudaMemsetAsync(bar_ptr,  0, sizeof(int));

    kernelA<<<A_BLOCKS, 256>>>(x, Wm, Wl, Wg, dst);
    kernelB<<<B_BLOCKS, 256>>>(src, dst, alpha, beta, Watt, batt, out);
}

// round 7
// speedup vs baseline: 1.2338x; 1.2338x over previous
#include <cuda_runtime.h>
#include <cuda_bf16.h>

#define N_NODES 100000
#define N_EDGES 3200000
#define IN_CH   256

// Scratch (device globals: allocation APIs are forbidden)
__device__ float g_xm[N_NODES];    // x @ W_mlp
__device__ float g_xl[N_NODES];    // x @ W_lin
__device__ float g_xw[N_NODES];    // x @ W_gcn
__device__ float g_degf[N_NODES];  // in-degree (float, exact: deg << 2^24)
__device__ float g_h[N_NODES];     // rsqrt(deg+1) * xw
__device__ float g_gcn[N_NODES];   // accumulates sum_s h[s]

#define DOT_BLOCKS 592                     // every 4th block of the fused grid
#define FUSED_BLOCKS (DOT_BLOCKS * 4)      // 2368
#define DEG_BLOCKS (FUSED_BLOCKS - DOT_BLOCKS) // 1776
#define DOT_WARPS  (DOT_BLOCKS * 8)        // 4736
#define EQUADS     (N_EDGES / 4)           // 800000 int4 groups
#define EGROUPS    (N_EDGES / 8)           // 400000 (msg: 2 int4 per thread)
#define MSG_BLOCKS ((EGROUPS + 255) / 256) // 1563

// ---------------------------------------------------------------------------
__device__ __forceinline__ void dot3(const float4 a0, const float4 a1,
                                     const float4 m0, const float4 m1,
                                     const float4 l0, const float4 l1,
                                     const float4 g0, const float4 g1,
                                     float& sm, float& sl, float& sg) {
    sm = a0.x*m0.x + a0.y*m0.y + a0.z*m0.z + a0.w*m0.w
       + a1.x*m1.x + a1.y*m1.y + a1.z*m1.z + a1.w*m1.w;
    sl = a0.x*l0.x + a0.y*l0.y + a0.z*l0.z + a0.w*l0.w
       + a1.x*l1.x + a1.y*l1.y + a1.z*l1.z + a1.w*l1.w;
    sg = a0.x*g0.x + a0.y*g0.y + a0.z*g0.z + a0.w*g0.w
       + a1.x*g1.x + a1.y*g1.y + a1.z*g1.z + a1.w*g1.w;
}

// ---------------------------------------------------------------------------
// Fused dots + degree with INTERLEAVED roles: blockIdx.x % 4 == 0 -> dots
// (persistent warp-per-node loop), else -> degree atomics (grid-stride).
// Interleaving keeps both kinds of blocks co-resident in every wave, so the
// DRAM-bound dots stream overlaps the L2-atomic-bound degree pass.
__global__ void __launch_bounds__(256) fused_dots_deg_kernel(
        const float* __restrict__ x,
        const float* __restrict__ Wm,
        const float* __restrict__ Wl,
        const float* __restrict__ Wg,
        const int*   __restrict__ dst) {
    if ((blockIdx.x & 3) == 0) {
        // ---- dots role: 592 blocks ----
        int db   = blockIdx.x >> 2;                   // 0..591
        int wid  = (db * 256 + threadIdx.x) >> 5;
        int lane = threadIdx.x & 31;
        int i0 = lane, i1 = lane + 32;

        const float4* wm4 = (const float4*)Wm;
        const float4* wl4 = (const float4*)Wl;
        const float4* wg4 = (const float4*)Wg;
        float4 m0 = __ldg(&wm4[i0]), m1 = __ldg(&wm4[i1]);
        float4 l0 = __ldg(&wl4[i0]), l1 = __ldg(&wl4[i1]);
        float4 g0 = __ldg(&wg4[i0]), g1 = __ldg(&wg4[i1]);

        const int stride = DOT_WARPS;
        for (int n0 = wid; n0 < N_NODES; n0 += 4 * stride) {
            int n1 = n0 + stride;
            int n2 = n0 + 2 * stride;
            int n3 = n0 + 3 * stride;
            bool h1 = n1 < N_NODES, h2 = n2 < N_NODES, h3 = n3 < N_NODES;

            const float4* x0 = (const float4*)(x + (size_t)n0 * IN_CH);
            const float4* x1 = (const float4*)(x + (size_t)(h1 ? n1 : n0) * IN_CH);
            const float4* x2 = (const float4*)(x + (size_t)(h2 ? n2 : n0) * IN_CH);
            const float4* x3 = (const float4*)(x + (size_t)(h3 ? n3 : n0) * IN_CH);

            float4 a0 = x0[i0], a1 = x0[i1];
            float4 b0 = x1[i0], b1 = x1[i1];
            float4 c0 = x2[i0], c1 = x2[i1];
            float4 d0 = x3[i0], d1 = x3[i1];

            float smA, slA, sgA, smB, slB, sgB, smC, slC, sgC, smD, slD, sgD;
            dot3(a0, a1, m0, m1, l0, l1, g0, g1, smA, slA, sgA);
            dot3(b0, b1, m0, m1, l0, l1, g0, g1, smB, slB, sgB);
            dot3(c0, c1, m0, m1, l0, l1, g0, g1, smC, slC, sgC);
            dot3(d0, d1, m0, m1, l0, l1, g0, g1, smD, slD, sgD);

#pragma unroll
            for (int o = 16; o > 0; o >>= 1) {
                smA += __shfl_xor_sync(0xffffffffu, smA, o);
                slA += __shfl_xor_sync(0xffffffffu, slA, o);
                sgA += __shfl_xor_sync(0xffffffffu, sgA, o);
                smB += __shfl_xor_sync(0xffffffffu, smB, o);
                slB += __shfl_xor_sync(0xffffffffu, slB, o);
                sgB += __shfl_xor_sync(0xffffffffu, sgB, o);
                smC += __shfl_xor_sync(0xffffffffu, smC, o);
                slC += __shfl_xor_sync(0xffffffffu, slC, o);
                sgC += __shfl_xor_sync(0xffffffffu, sgC, o);
                smD += __shfl_xor_sync(0xffffffffu, smD, o);
                slD += __shfl_xor_sync(0xffffffffu, slD, o);
                sgD += __shfl_xor_sync(0xffffffffu, sgD, o);
            }
            if (lane == 0) {
                g_xm[n0] = smA; g_xl[n0] = slA; g_xw[n0] = sgA;
                if (h1) { g_xm[n1] = smB; g_xl[n1] = slB; g_xw[n1] = sgB; }
                if (h2) { g_xm[n2] = smC; g_xl[n2] = slC; g_xw[n2] = sgC; }
                if (h3) { g_xm[n3] = smD; g_xl[n3] = slD; g_xw[n3] = sgD; }
            }
        }
    } else {
        // ---- degree role: 1776 blocks, grid-stride over 800k int4 groups ----
        int eb = blockIdx.x - (blockIdx.x >> 2) - 1;  // 0..1775
        int t = eb * 256 + threadIdx.x;
        const int stride = DEG_BLOCKS * 256;
        const int4* d4p = (const int4*)dst;
        for (; t < EQUADS; t += stride) {
            int4 a = d4p[t];
            atomicAdd(&g_degf[a.x], 1.0f);
            atomicAdd(&g_degf[a.y], 1.0f);
            atomicAdd(&g_degf[a.z], 1.0f);
            atomicAdd(&g_degf[a.w], 1.0f);
        }
    }
}

// ---------------------------------------------------------------------------
// h[n] = rsqrt(deg+1) * xw[n] — single gather stream for msg.
__global__ void __launch_bounds__(256) h_kernel() {
    int n = blockIdx.x * 256 + threadIdx.x;
    if (n < N_NODES) {
        g_h[n] = rsqrtf(g_degf[n] + 1.0f) * g_xw[n];
    }
}

// ---------------------------------------------------------------------------
// Edge messages: gcn[d] += h[s]  (dinv[d] applied in final). 8 edges/thread,
// all gathers batched before the atomics.
__global__ void __launch_bounds__(256) msg_kernel(const int* __restrict__ src,
                                                  const int* __restrict__ dst) {
    int t = blockIdx.x * 256 + threadIdx.x;
    if (t >= EGROUPS) return;
    const int4* s4p = (const int4*)src;
    const int4* d4p = (const int4*)dst;
    int4 sa = s4p[t];
    int4 sb = s4p[t + EGROUPS];
    int4 da = d4p[t];
    int4 db = d4p[t + EGROUPS];

    float h0 = __ldg(&g_h[sa.x]);
    float h1 = __ldg(&g_h[sa.y]);
    float h2 = __ldg(&g_h[sa.z]);
    float h3 = __ldg(&g_h[sa.w]);
    float h4 = __ldg(&g_h[sb.x]);
    float h5 = __ldg(&g_h[sb.y]);
    float h6 = __ldg(&g_h[sb.z]);
    float h7 = __ldg(&g_h[sb.w]);

    atomicAdd(&g_gcn[da.x], h0);
    atomicAdd(&g_gcn[da.y], h1);
    atomicAdd(&g_gcn[da.z], h2);
    atomicAdd(&g_gcn[da.w], h3);
    atomicAdd(&g_gcn[db.x], h4);
    atomicAdd(&g_gcn[db.y], h5);
    atomicAdd(&g_gcn[db.z], h6);
    atomicAdd(&g_gcn[db.w], h7);
}

__device__ __forceinline__ float sigmoidf_(float v) {
    return 1.0f / (1.0f + expf(-v));
}

// ---------------------------------------------------------------------------
__global__ void __launch_bounds__(256) final_kernel(
        const float* __restrict__ alpha_p,
        const float* __restrict__ beta_p,
        const float* __restrict__ W_att,
        const float* __restrict__ b_att,
        float* __restrict__ out) {
    int n = blockIdx.x * 256 + threadIdx.x;
    if (n >= N_NODES) return;

    float alpha = __ldg(alpha_p);
    float beta  = __ldg(beta_p);

    float degf = g_degf[n];
    float dinv = rsqrtf(degf + 1.0f);
    float gcn  = dinv * (g_gcn[n] + g_h[n]);   // h[n] = dinv*xw[n]

    float s1 = sigmoidf_(alpha * sqrtf(degf) + beta);
    float s2 = sigmoidf_(g_xm[n]);
    float s3 = sigmoidf_(gcn + g_xl[n]);

    float l0 = s1 * __ldg(&W_att[0]) + s2 * __ldg(&W_att[1]) + s3 * __ldg(&W_att[2]) + __ldg(&b_att[0]);
    float l1 = s1 * __ldg(&W_att[3]) + s2 * __ldg(&W_att[4]) + s3 * __ldg(&W_att[5]) + __ldg(&b_att[1]);
    float l2 = s1 * __ldg(&W_att[6]) + s2 * __ldg(&W_att[7]) + s3 * __ldg(&W_att[8]) + __ldg(&b_att[2]);

    float m  = fmaxf(l0, fmaxf(l1, l2));
    float e0 = expf(l0 - m), e1 = expf(l1 - m), e2 = expf(l2 - m);
    float inv = 1.0f / (e0 + e1 + e2);
    out[n] = (e0 * s1 + e1 * s2 + e2 * s3) * inv;
}

// ---------------------------------------------------------------------------
extern "C" void kernel_launch(void* const* d_in, const int* in_sizes, int n_in,
                              void* d_out, int out_size) {
    const float* x     = (const float*)d_in[0];
    const int*   eidx  = (const int*)d_in[1];   // [2, N_EDGES] int32
    const float* alpha = (const float*)d_in[2];
    const float* beta  = (const float*)d_in[3];
    const float* Wm    = (const float*)d_in[4];
    const float* Wl    = (const float*)d_in[5];
    const float* Wg    = (const float*)d_in[6];
    const float* Watt  = (const float*)d_in[7];
    const float* batt  = (const float*)d_in[8];
    float* out = (float*)d_out;

    const int* src = eidx;            // edge_index[0]
    const int* dst = eidx + N_EDGES;  // edge_index[1]

    void *degf_ptr = nullptr, *gcn_ptr = nullptr;
    cudaGetSymbolAddress(&degf_ptr, g_degf);
    cudaGetSymbolAddress(&gcn_ptr,  g_gcn);
    cudaMemsetAsync(degf_ptr, 0, N_NODES * sizeof(float));
    cudaMemsetAsync(gcn_ptr,  0, N_NODES * sizeof(float));

    int nodeBlocks = (N_NODES + 255) / 256;

    fused_dots_deg_kernel<<<FUSED_BLOCKS, 256>>>(x, Wm, Wl, Wg, dst);
    h_kernel<<<nodeBlocks, 256>>>();
    msg_kernel<<<MSG_BLOCKS, 256>>>(src, dst);
    final_kernel<<<nodeBlocks, 256>>>(alpha, beta, Watt, batt, out);
}